// round 1
// baseline (speedup 1.0000x reference)
#include <cuda_runtime.h>
#include <mma.h>
#include <math.h>

using namespace nvcuda;

#define BATCH 8192
#define EMBED 256
#define HID   256
#define VOCAB 32000
#define KIN   768   // EMBED + 2*HID
#define KC    512   // EMBED + HID

// ============================================================================
// Kernel 1: fused LSTM gates.
//   For a 64(batch) x 64(hid) tile, compute all four gate pre-activations
//   (forget/update/output over lstm_in[768], candidate over lstm_in[256:768])
//   with 3xTF32 WMMA (fp32-grade accuracy), then apply the full elementwise
//   LSTM epilogue and write c_t, h_t. lstm_in is gathered on the fly.
// ============================================================================

#define G_BM 64
#define G_BN 64
#define G_BK 16
#define G_LD 20   // padded row (floats); 80B = multiple of 16B for wmma ldm

// smem: main phase needs 5*64*20 = 6400 floats (A + 4 B tiles)
//       epilogue staging needs 8 warps * 4 gates * 16*20 = 10240 floats
#define G_SMEM 10240

__global__ __launch_bounds__(256) void lstm_gates_kernel(
    const float* __restrict__ x, const float* __restrict__ c_prev,
    const float* __restrict__ h_prev,
    const float* __restrict__ Wf, const float* __restrict__ bf,
    const float* __restrict__ Wu, const float* __restrict__ bu,
    const float* __restrict__ Wo, const float* __restrict__ bo,
    const float* __restrict__ Wc, const float* __restrict__ bc,
    float* __restrict__ c_out, float* __restrict__ h_out)
{
    __shared__ float smem[G_SMEM];
    float* As = smem;                       // [64][G_LD]
    float* Bs = smem + G_BM * G_LD;         // [4][64][G_LD]

    const int tid = threadIdx.x;
    const int w   = tid >> 5;
    const int lane = tid & 31;
    const int wm  = w & 3;     // 4 row subtiles of 16
    const int wn  = w >> 2;    // 2 col subtiles of 32
    const int m0  = blockIdx.y * G_BM;
    const int n0  = blockIdx.x * G_BN;

    wmma::fragment<wmma::accumulator, 16, 16, 8, float> acc[4][2];
    #pragma unroll
    for (int g = 0; g < 4; g++)
        #pragma unroll
        for (int nf = 0; nf < 2; nf++)
            wmma::fill_fragment(acc[g][nf], 0.0f);

    for (int k0 = 0; k0 < KIN; k0 += G_BK) {
        // --- load A tile (gathered lstm_in = [c_prev, h_prev, x]) ---
        #pragma unroll
        for (int t = tid; t < G_BM * G_BK; t += 256) {
            int r = t >> 4, c = t & 15;
            int gk = k0 + c;
            int row = m0 + r;
            float v;
            if (gk < HID)            v = c_prev[row * HID + gk];
            else if (gk < 2 * HID)   v = h_prev[row * HID + (gk - HID)];
            else                     v = x[row * EMBED + (gk - 2 * HID)];
            As[r * G_LD + c] = v;
        }
        // --- load B tiles: Wf, Wu, Wo (always); Wc only for k0 >= HID ---
        #pragma unroll
        for (int t = tid; t < G_BN * G_BK; t += 256) {
            int j = t >> 4, c = t & 15;
            int widx = (n0 + j) * KIN + k0 + c;
            Bs[(0 * G_BM + j) * G_LD + c] = Wf[widx];
            Bs[(1 * G_BM + j) * G_LD + c] = Wu[widx];
            Bs[(2 * G_BM + j) * G_LD + c] = Wo[widx];
        }
        if (k0 >= HID) {
            #pragma unroll
            for (int t = tid; t < G_BN * G_BK; t += 256) {
                int j = t >> 4, c = t & 15;
                Bs[(3 * G_BM + j) * G_LD + c] = Wc[(n0 + j) * KC + (k0 - HID) + c];
            }
        }
        __syncthreads();

        const int ng = (k0 >= HID) ? 4 : 3;
        #pragma unroll
        for (int ks = 0; ks < G_BK; ks += 8) {
            wmma::fragment<wmma::matrix_a, 16, 16, 8, wmma::precision::tf32, wmma::row_major> a_hi, a_lo;
            wmma::load_matrix_sync(a_hi, &As[(wm * 16) * G_LD + ks], G_LD);
            #pragma unroll
            for (int i = 0; i < a_hi.num_elements; i++) {
                float v  = a_hi.x[i];
                float hi = wmma::__float_to_tf32(v);
                a_hi.x[i] = hi;
                a_lo.x[i] = wmma::__float_to_tf32(v - hi);
            }
            for (int g = 0; g < ng; g++) {
                #pragma unroll
                for (int nf = 0; nf < 2; nf++) {
                    wmma::fragment<wmma::matrix_b, 16, 16, 8, wmma::precision::tf32, wmma::col_major> b_hi, b_lo;
                    wmma::load_matrix_sync(b_hi, &Bs[(g * G_BM + wn * 32 + nf * 16) * G_LD + ks], G_LD);
                    #pragma unroll
                    for (int i = 0; i < b_hi.num_elements; i++) {
                        float v  = b_hi.x[i];
                        float hi = wmma::__float_to_tf32(v);
                        b_hi.x[i] = hi;
                        b_lo.x[i] = wmma::__float_to_tf32(v - hi);
                    }
                    wmma::mma_sync(acc[g][nf], a_hi, b_hi, acc[g][nf]);
                    wmma::mma_sync(acc[g][nf], a_hi, b_lo, acc[g][nf]);
                    wmma::mma_sync(acc[g][nf], a_lo, b_hi, acc[g][nf]);
                }
            }
        }
        __syncthreads();
    }

    // --- epilogue: stage the four gate tiles per warp, combine elementwise ---
    float* stg = smem + w * (4 * 16 * G_LD);   // per-warp private region
    #pragma unroll
    for (int nf = 0; nf < 2; nf++) {
        #pragma unroll
        for (int g = 0; g < 4; g++)
            wmma::store_matrix_sync(stg + g * 16 * G_LD, acc[g][nf], G_LD, wmma::mem_row_major);
        __syncwarp();
        #pragma unroll
        for (int e = lane; e < 256; e += 32) {
            int r  = e >> 4, cc = e & 15;
            int row = m0 + wm * 16 + r;
            int col = n0 + wn * 32 + nf * 16 + cc;
            float zf = stg[0 * 16 * G_LD + r * G_LD + cc] + bf[col];
            float zu = stg[1 * 16 * G_LD + r * G_LD + cc] + bu[col];
            float zo = stg[2 * 16 * G_LD + r * G_LD + cc] + bo[col];
            float zc = stg[3 * 16 * G_LD + r * G_LD + cc] + bc[col];
            float fg = 1.0f / (1.0f + expf(-zf));
            float ug = 1.0f / (1.0f + expf(-zu));
            float og = 1.0f / (1.0f + expf(-zo));
            float cn = tanhf(zc);
            float cp = c_prev[row * HID + col];
            float ct = fg * cp + ug * cn;
            float ht = og * tanhf(ct);
            c_out[row * HID + col] = ct;
            h_out[row * HID + col] = ht;
        }
        __syncwarp();
    }
}

// ============================================================================
// Kernel 2: logits GEMM  y[8192,32000] = h @ Wl.T + bl, 3xTF32 WMMA.
//   Block tile 128x128, BK=16, 8 warps (4x2), each warp 32x64 (2x4 frags).
// ============================================================================

#define Y_BM 128
#define Y_BN 128
#define Y_BK 16
#define Y_LD 20

#define Y_SMEM (2 * 128 * Y_LD)   // 5120 floats; epilogue staging 8*16*20=2560 fits

__global__ __launch_bounds__(256) void lstm_logits_kernel(
    const float* __restrict__ h, const float* __restrict__ Wl,
    const float* __restrict__ bl, float* __restrict__ y)
{
    __shared__ float smem[Y_SMEM];
    float* As = smem;                  // [128][Y_LD]  (h rows)
    float* Bs = smem + 128 * Y_LD;     // [128][Y_LD]  (Wl rows = vocab cols)

    const int tid  = threadIdx.x;
    const int w    = tid >> 5;
    const int lane = tid & 31;
    const int wm   = w >> 1;   // 4 row subtiles of 32
    const int wn   = w & 1;    // 2 col subtiles of 64
    const int m0   = blockIdx.y * Y_BM;
    const int n0   = blockIdx.x * Y_BN;

    wmma::fragment<wmma::accumulator, 16, 16, 8, float> acc[2][4];
    #pragma unroll
    for (int mf = 0; mf < 2; mf++)
        #pragma unroll
        for (int nf = 0; nf < 4; nf++)
            wmma::fill_fragment(acc[mf][nf], 0.0f);

    for (int k0 = 0; k0 < HID; k0 += Y_BK) {
        #pragma unroll
        for (int t = tid; t < 128 * Y_BK; t += 256) {
            int r = t >> 4, c = t & 15;
            As[r * Y_LD + c] = h[(m0 + r) * HID + k0 + c];
            Bs[r * Y_LD + c] = Wl[(n0 + r) * HID + k0 + c];
        }
        __syncthreads();

        #pragma unroll
        for (int ks = 0; ks < Y_BK; ks += 8) {
            wmma::fragment<wmma::matrix_a, 16, 16, 8, wmma::precision::tf32, wmma::row_major> a_hi[2], a_lo[2];
            #pragma unroll
            for (int mf = 0; mf < 2; mf++) {
                wmma::load_matrix_sync(a_hi[mf], &As[(wm * 32 + mf * 16) * Y_LD + ks], Y_LD);
                #pragma unroll
                for (int i = 0; i < a_hi[mf].num_elements; i++) {
                    float v  = a_hi[mf].x[i];
                    float hi = wmma::__float_to_tf32(v);
                    a_hi[mf].x[i] = hi;
                    a_lo[mf].x[i] = wmma::__float_to_tf32(v - hi);
                }
            }
            #pragma unroll
            for (int nf = 0; nf < 4; nf++) {
                wmma::fragment<wmma::matrix_b, 16, 16, 8, wmma::precision::tf32, wmma::col_major> b_hi, b_lo;
                wmma::load_matrix_sync(b_hi, &Bs[(wn * 64 + nf * 16) * Y_LD + ks], Y_LD);
                #pragma unroll
                for (int i = 0; i < b_hi.num_elements; i++) {
                    float v  = b_hi.x[i];
                    float hi = wmma::__float_to_tf32(v);
                    b_hi.x[i] = hi;
                    b_lo.x[i] = wmma::__float_to_tf32(v - hi);
                }
                #pragma unroll
                for (int mf = 0; mf < 2; mf++) {
                    wmma::mma_sync(acc[mf][nf], a_hi[mf], b_hi, acc[mf][nf]);
                    wmma::mma_sync(acc[mf][nf], a_hi[mf], b_lo, acc[mf][nf]);
                    wmma::mma_sync(acc[mf][nf], a_lo[mf], b_hi, acc[mf][nf]);
                }
            }
        }
        __syncthreads();
    }

    // --- epilogue: stage per-fragment, add bias, write coalesced-ish ---
    float* stg = smem + w * (16 * Y_LD);
    #pragma unroll
    for (int mf = 0; mf < 2; mf++) {
        #pragma unroll
        for (int nf = 0; nf < 4; nf++) {
            wmma::store_matrix_sync(stg, acc[mf][nf], Y_LD, wmma::mem_row_major);
            __syncwarp();
            #pragma unroll
            for (int e = lane; e < 256; e += 32) {
                int r  = e >> 4, cc = e & 15;
                size_t row = (size_t)(m0 + wm * 32 + mf * 16 + r);
                int    col = n0 + wn * 64 + nf * 16 + cc;
                y[row * VOCAB + col] = stg[r * Y_LD + cc] + bl[col];
            }
            __syncwarp();
        }
    }
}

// ============================================================================
// Launch
// ============================================================================

extern "C" void kernel_launch(void* const* d_in, const int* in_sizes, int n_in,
                              void* d_out, int out_size)
{
    const float* x      = (const float*)d_in[0];
    const float* c_prev = (const float*)d_in[1];
    const float* h_prev = (const float*)d_in[2];
    const float* Wf     = (const float*)d_in[3];
    const float* bf     = (const float*)d_in[4];
    const float* Wu     = (const float*)d_in[5];
    const float* bu     = (const float*)d_in[6];
    const float* Wo     = (const float*)d_in[7];
    const float* bo     = (const float*)d_in[8];
    const float* Wc     = (const float*)d_in[9];
    const float* bc     = (const float*)d_in[10];
    const float* Wl     = (const float*)d_in[11];
    const float* bl     = (const float*)d_in[12];

    float* out   = (float*)d_out;
    float* c_out = out;                       // [8192, 256]
    float* h_out = out + (size_t)BATCH * HID; // [8192, 256]
    float* y_out = out + (size_t)2 * BATCH * HID; // [8192, 32000]

    dim3 g1(HID / G_BN, BATCH / G_BM);   // (4, 128)
    lstm_gates_kernel<<<g1, 256>>>(x, c_prev, h_prev, Wf, bf, Wu, bu,
                                   Wo, bo, Wc, bc, c_out, h_out);

    dim3 g2(VOCAB / Y_BN, BATCH / Y_BM); // (250, 64)
    lstm_logits_kernel<<<g2, 256>>>(h_out, Wl, bl, y_out);
}

// round 3
// speedup vs baseline: 2.7615x; 2.7615x over previous
#include <cuda_runtime.h>
#include <cuda_bf16.h>
#include <mma.h>
#include <math.h>
#include <cstdint>

using namespace nvcuda;

#define BATCH 8192
#define EMBED 256
#define HID   256
#define VOCAB 32000
#define KIN   768   // EMBED + 2*HID
#define KC    512   // EMBED + HID
#define KPACK 768   // 3 x 256 packed split-K

// ============================================================================
// Device scratch: packed bf16 split operands (static globals — no allocation)
//   A2[b][k] : k in [0,256)=h_hi, [256,512)=h_lo, [512,768)=h_hi
//   B2[v][k] : k in [0,256)=Wl_hi, [256,512)=Wl_hi, [512,768)=Wl_lo
//   => A2 . B2^T = Ah Bh + Al Bh + Ah Bl  (error-compensated bf16 product)
// ============================================================================
__device__ __nv_bfloat16 g_A2[(size_t)BATCH * KPACK];
__device__ __nv_bfloat16 g_B2[(size_t)VOCAB * KPACK];

// ============================================================================
// PTX helpers (all plain sm_80-era features — safe under .target sm_103)
// ============================================================================
__device__ __forceinline__ uint32_t smem_to_u32(const void* p) {
    uint32_t a;
    asm("{ .reg .u64 t; cvta.to.shared.u64 t, %1; cvt.u32.u64 %0, t; }" : "=r"(a) : "l"(p));
    return a;
}
#define CP_ASYNC16(dst, src) asm volatile("cp.async.cg.shared.global [%0], [%1], 16;" :: "r"(dst), "l"(src) : "memory")
#define CP_COMMIT()  asm volatile("cp.async.commit_group;" ::: "memory")
#define CP_WAIT(N)   asm volatile("cp.async.wait_group %0;" :: "n"(N) : "memory")

#define LDMATRIX_X4(r0, r1, r2, r3, addr) \
    asm volatile("ldmatrix.sync.aligned.m8n8.x4.shared.b16 {%0,%1,%2,%3}, [%4];" \
        : "=r"(r0), "=r"(r1), "=r"(r2), "=r"(r3) : "r"(addr))

#define MMA_BF16(d, a, b) \
    asm volatile("mma.sync.aligned.m16n8k16.row.col.f32.bf16.bf16.f32 " \
        "{%0,%1,%2,%3}, {%4,%5,%6,%7}, {%8,%9}, {%0,%1,%2,%3};" \
        : "+f"((d)[0]), "+f"((d)[1]), "+f"((d)[2]), "+f"((d)[3]) \
        : "r"((a)[0]), "r"((a)[1]), "r"((a)[2]), "r"((a)[3]), \
          "r"((b)[0]), "r"((b)[1]))

// ============================================================================
// pack kernels: fp32 [rows,256] -> bf16 [rows,768] hi/lo/hi (or hi/hi/lo)
// ============================================================================
__global__ __launch_bounds__(256) void pack_split(
    const float* __restrict__ src, __nv_bfloat16* __restrict__ dst,
    int n4, int hi2_off, int lo_off)
{
    int i = blockIdx.x * 256 + threadIdx.x;
    if (i >= n4) return;
    int row = i >> 6;          // 64 float4 per 256-col row
    int c4  = (i & 63) * 4;
    float4 v = ((const float4*)src)[i];
    __nv_bfloat16 h0 = __float2bfloat16_rn(v.x);
    __nv_bfloat16 h1 = __float2bfloat16_rn(v.y);
    __nv_bfloat16 h2 = __float2bfloat16_rn(v.z);
    __nv_bfloat16 h3 = __float2bfloat16_rn(v.w);
    __nv_bfloat162 H0, H1, L0, L1;
    H0.x = h0; H0.y = h1; H1.x = h2; H1.y = h3;
    L0.x = __float2bfloat16_rn(v.x - __bfloat162float(h0));
    L0.y = __float2bfloat16_rn(v.y - __bfloat162float(h1));
    L1.x = __float2bfloat16_rn(v.z - __bfloat162float(h2));
    L1.y = __float2bfloat16_rn(v.w - __bfloat162float(h3));
    size_t base = (size_t)row * KPACK;
    __nv_bfloat162* dh  = (__nv_bfloat162*)(dst + base + c4);
    __nv_bfloat162* dh2 = (__nv_bfloat162*)(dst + base + hi2_off + c4);
    __nv_bfloat162* dl  = (__nv_bfloat162*)(dst + base + lo_off + c4);
    dh[0]  = H0; dh[1]  = H1;
    dh2[0] = H0; dh2[1] = H1;
    dl[0]  = L0; dl[1]  = L1;
}

// ============================================================================
// Kernel 1: fused LSTM gates (3xTF32 WMMA — unchanged, known correct)
// ============================================================================
#define G_BM 64
#define G_BN 64
#define G_BK 16
#define G_LD 20
#define G_SMEM 10240

__global__ __launch_bounds__(256) void lstm_gates_kernel(
    const float* __restrict__ x, const float* __restrict__ c_prev,
    const float* __restrict__ h_prev,
    const float* __restrict__ Wf, const float* __restrict__ bf,
    const float* __restrict__ Wu, const float* __restrict__ bu,
    const float* __restrict__ Wo, const float* __restrict__ bo,
    const float* __restrict__ Wc, const float* __restrict__ bc,
    float* __restrict__ c_out, float* __restrict__ h_out)
{
    __shared__ float smem[G_SMEM];
    float* As = smem;
    float* Bs = smem + G_BM * G_LD;

    const int tid = threadIdx.x;
    const int w   = tid >> 5;
    const int lane = tid & 31;
    const int wm  = w & 3;
    const int wn  = w >> 2;
    const int m0  = blockIdx.y * G_BM;
    const int n0  = blockIdx.x * G_BN;

    wmma::fragment<wmma::accumulator, 16, 16, 8, float> acc[4][2];
    #pragma unroll
    for (int g = 0; g < 4; g++)
        #pragma unroll
        for (int nf = 0; nf < 2; nf++)
            wmma::fill_fragment(acc[g][nf], 0.0f);

    for (int k0 = 0; k0 < KIN; k0 += G_BK) {
        #pragma unroll
        for (int t = tid; t < G_BM * G_BK; t += 256) {
            int r = t >> 4, c = t & 15;
            int gk = k0 + c;
            int row = m0 + r;
            float v;
            if (gk < HID)            v = c_prev[row * HID + gk];
            else if (gk < 2 * HID)   v = h_prev[row * HID + (gk - HID)];
            else                     v = x[row * EMBED + (gk - 2 * HID)];
            As[r * G_LD + c] = v;
        }
        #pragma unroll
        for (int t = tid; t < G_BN * G_BK; t += 256) {
            int j = t >> 4, c = t & 15;
            int widx = (n0 + j) * KIN + k0 + c;
            Bs[(0 * G_BM + j) * G_LD + c] = Wf[widx];
            Bs[(1 * G_BM + j) * G_LD + c] = Wu[widx];
            Bs[(2 * G_BM + j) * G_LD + c] = Wo[widx];
        }
        if (k0 >= HID) {
            #pragma unroll
            for (int t = tid; t < G_BN * G_BK; t += 256) {
                int j = t >> 4, c = t & 15;
                Bs[(3 * G_BM + j) * G_LD + c] = Wc[(n0 + j) * KC + (k0 - HID) + c];
            }
        }
        __syncthreads();

        const int ng = (k0 >= HID) ? 4 : 3;
        #pragma unroll
        for (int ks = 0; ks < G_BK; ks += 8) {
            wmma::fragment<wmma::matrix_a, 16, 16, 8, wmma::precision::tf32, wmma::row_major> a_hi, a_lo;
            wmma::load_matrix_sync(a_hi, &As[(wm * 16) * G_LD + ks], G_LD);
            #pragma unroll
            for (int i = 0; i < a_hi.num_elements; i++) {
                float v  = a_hi.x[i];
                float hi = wmma::__float_to_tf32(v);
                a_hi.x[i] = hi;
                a_lo.x[i] = wmma::__float_to_tf32(v - hi);
            }
            for (int g = 0; g < ng; g++) {
                #pragma unroll
                for (int nf = 0; nf < 2; nf++) {
                    wmma::fragment<wmma::matrix_b, 16, 16, 8, wmma::precision::tf32, wmma::col_major> b_hi, b_lo;
                    wmma::load_matrix_sync(b_hi, &Bs[(g * G_BM + wn * 32 + nf * 16) * G_LD + ks], G_LD);
                    #pragma unroll
                    for (int i = 0; i < b_hi.num_elements; i++) {
                        float v  = b_hi.x[i];
                        float hi = wmma::__float_to_tf32(v);
                        b_hi.x[i] = hi;
                        b_lo.x[i] = wmma::__float_to_tf32(v - hi);
                    }
                    wmma::mma_sync(acc[g][nf], a_hi, b_hi, acc[g][nf]);
                    wmma::mma_sync(acc[g][nf], a_hi, b_lo, acc[g][nf]);
                    wmma::mma_sync(acc[g][nf], a_lo, b_hi, acc[g][nf]);
                }
            }
        }
        __syncthreads();
    }

    float* stg = smem + w * (4 * 16 * G_LD);
    #pragma unroll
    for (int nf = 0; nf < 2; nf++) {
        #pragma unroll
        for (int g = 0; g < 4; g++)
            wmma::store_matrix_sync(stg + g * 16 * G_LD, acc[g][nf], G_LD, wmma::mem_row_major);
        __syncwarp();
        #pragma unroll
        for (int e = lane; e < 256; e += 32) {
            int r  = e >> 4, cc = e & 15;
            int row = m0 + wm * 16 + r;
            int col = n0 + wn * 32 + nf * 16 + cc;
            float zf = stg[0 * 16 * G_LD + r * G_LD + cc] + bf[col];
            float zu = stg[1 * 16 * G_LD + r * G_LD + cc] + bu[col];
            float zo = stg[2 * 16 * G_LD + r * G_LD + cc] + bo[col];
            float zc = stg[3 * 16 * G_LD + r * G_LD + cc] + bc[col];
            float fg = 1.0f / (1.0f + expf(-zf));
            float ug = 1.0f / (1.0f + expf(-zu));
            float og = 1.0f / (1.0f + expf(-zo));
            float cn = tanhf(zc);
            float cp = c_prev[row * HID + col];
            float ct = fg * cp + ug * cn;
            float ht = og * tanhf(ct);
            c_out[row * HID + col] = ct;
            h_out[row * HID + col] = ht;
        }
        __syncwarp();
    }
}

// ============================================================================
// Kernel 2: logits GEMM  y = A2 . B2^T + bl  (bf16 mma.sync, K=768)
//   Block 128x128, BK=64, 2-stage cp.async pipeline, 8 warps (4x2),
//   warp tile 32x64 = 2 m-frags x 8 n-frags of m16n8k16.
// ============================================================================
#define L_BM 128
#define L_BN 128
#define L_BK 64
#define L_NSTAGE 12          // 768 / 64
#define LDAB 72              // halfs per smem row (144B, 16B-aligned, conflict-free)
#define A_BYTES (L_BM * LDAB * 2)
#define STAGE_BYTES (2 * A_BYTES)     // A tile + B tile
#define L_SMEM (2 * STAGE_BYTES)      // 73728 bytes

__global__ __launch_bounds__(256) void lstm_logits_mma(
    const float* __restrict__ bl, float* __restrict__ y)
{
    extern __shared__ char smem[];
    const uint32_t sb = smem_to_u32(smem);
    const int tid  = threadIdx.x;
    const int w    = tid >> 5;
    const int lane = tid & 31;
    const int wr   = (w >> 1) * 32;   // warp row offset in block tile
    const int wc   = (w & 1) * 64;    // warp col offset
    const int m0   = blockIdx.y * L_BM;
    const int n0   = blockIdx.x * L_BN;

    const __nv_bfloat16* Ag = g_A2;
    const __nv_bfloat16* Bg = g_B2;

    float acc[2][8][4];
    #pragma unroll
    for (int mf = 0; mf < 2; mf++)
        #pragma unroll
        for (int nf = 0; nf < 8; nf++)
            #pragma unroll
            for (int i = 0; i < 4; i++)
                acc[mf][nf][i] = 0.0f;

    // per-thread cp.async assignments: 1024 16B-chunks per tile, 256 threads
    // chunk u: row = u>>3, c8 = u&7  (8 chunks of 16B per 128B row)
    auto load_stage = [&](int buf, int k0) {
        uint32_t sA = sb + buf * STAGE_BYTES;
        uint32_t sB = sA + A_BYTES;
        #pragma unroll
        for (int it = 0; it < 4; it++) {
            int u = it * 256 + tid;
            int r = u >> 3, c8 = u & 7;
            uint32_t so = (uint32_t)(r * LDAB + c8 * 8) * 2;
            CP_ASYNC16(sA + so, (const void*)(Ag + (size_t)(m0 + r) * KPACK + k0 + c8 * 8));
            CP_ASYNC16(sB + so, (const void*)(Bg + (size_t)(n0 + r) * KPACK + k0 + c8 * 8));
        }
    };

    load_stage(0, 0);
    CP_COMMIT();

    for (int s = 0; s < L_NSTAGE; s++) {
        if (s + 1 < L_NSTAGE) {
            load_stage((s + 1) & 1, (s + 1) * L_BK);
            CP_COMMIT();
            CP_WAIT(1);
        } else {
            CP_WAIT(0);
        }
        __syncthreads();

        const uint32_t sA = sb + (s & 1) * STAGE_BYTES;
        const uint32_t sB = sA + A_BYTES;

        #pragma unroll
        for (int ks = 0; ks < 4; ks++) {
            // A fragments: 2 x m16k16 via ldmatrix.x4
            uint32_t a[2][4];
            {
                int kh = ks * 16 + (lane >> 4) * 8;
                #pragma unroll
                for (int mf = 0; mf < 2; mf++) {
                    int row = wr + mf * 16 + (lane & 15);
                    uint32_t ad = sA + (uint32_t)(row * LDAB + kh) * 2;
                    LDMATRIX_X4(a[mf][0], a[mf][1], a[mf][2], a[mf][3], ad);
                }
            }
            // B fragments: 8 x k16n8 via 4 ldmatrix.x4 (2 n-frags each)
            uint32_t b[8][2];
            {
                int kb = ks * 16 + ((lane >> 3) & 1) * 8;
                #pragma unroll
                for (int p = 0; p < 4; p++) {
                    int n = wc + p * 16 + (lane & 7) + ((lane >> 4) & 1) * 8;
                    uint32_t ad = sB + (uint32_t)(n * LDAB + kb) * 2;
                    LDMATRIX_X4(b[2 * p][0], b[2 * p][1], b[2 * p + 1][0], b[2 * p + 1][1], ad);
                }
            }
            #pragma unroll
            for (int mf = 0; mf < 2; mf++)
                #pragma unroll
                for (int nf = 0; nf < 8; nf++)
                    MMA_BF16(acc[mf][nf], a[mf], b[nf]);
        }
        __syncthreads();
    }

    // epilogue: direct float2 stores with bias
    #pragma unroll
    for (int mf = 0; mf < 2; mf++) {
        int r0 = m0 + wr + mf * 16 + (lane >> 2);
        #pragma unroll
        for (int nf = 0; nf < 8; nf++) {
            int c = n0 + wc + nf * 8 + (lane & 3) * 2;
            float2 bias = *(const float2*)(bl + c);
            float2 v0 = make_float2(acc[mf][nf][0] + bias.x, acc[mf][nf][1] + bias.y);
            float2 v1 = make_float2(acc[mf][nf][2] + bias.x, acc[mf][nf][3] + bias.y);
            *(float2*)(y + (size_t)r0 * VOCAB + c)       = v0;
            *(float2*)(y + (size_t)(r0 + 8) * VOCAB + c) = v1;
        }
    }
}

// ============================================================================
// Launch
// ============================================================================
extern "C" void kernel_launch(void* const* d_in, const int* in_sizes, int n_in,
                              void* d_out, int out_size)
{
    const float* x      = (const float*)d_in[0];
    const float* c_prev = (const float*)d_in[1];
    const float* h_prev = (const float*)d_in[2];
    const float* Wf     = (const float*)d_in[3];
    const float* bf     = (const float*)d_in[4];
    const float* Wu     = (const float*)d_in[5];
    const float* bu     = (const float*)d_in[6];
    const float* Wo     = (const float*)d_in[7];
    const float* bo     = (const float*)d_in[8];
    const float* Wc     = (const float*)d_in[9];
    const float* bc     = (const float*)d_in[10];
    const float* Wl     = (const float*)d_in[11];
    const float* bl     = (const float*)d_in[12];

    float* out   = (float*)d_out;
    float* c_out = out;
    float* h_out = out + (size_t)BATCH * HID;
    float* y_out = out + (size_t)2 * BATCH * HID;

    __nv_bfloat16 *a2, *b2;
    cudaGetSymbolAddress((void**)&a2, g_A2);
    cudaGetSymbolAddress((void**)&b2, g_B2);

    // 1) pack Wl -> B2 : hi at 0 and 256, lo at 512
    {
        int n4 = (VOCAB * HID) / 4;
        pack_split<<<(n4 + 255) / 256, 256>>>(Wl, b2, n4, 256, 512);
    }
    // 2) gates -> c_t, h_t
    dim3 g1(HID / G_BN, BATCH / G_BM);
    lstm_gates_kernel<<<g1, 256>>>(x, c_prev, h_prev, Wf, bf, Wu, bu,
                                   Wo, bo, Wc, bc, c_out, h_out);
    // 3) pack h_t -> A2 : hi at 0 and 512, lo at 256
    {
        int n4 = (BATCH * HID) / 4;
        pack_split<<<(n4 + 255) / 256, 256>>>(h_out, a2, n4, 512, 256);
    }
    // 4) logits
    cudaFuncSetAttribute(lstm_logits_mma, cudaFuncAttributeMaxDynamicSharedMemorySize, L_SMEM);
    dim3 g2(VOCAB / L_BN, BATCH / L_BM);   // (250, 64)
    lstm_logits_mma<<<g2, 256, L_SMEM>>>(bl, y_out);
}

// round 4
// speedup vs baseline: 5.1509x; 1.8653x over previous
#include <cuda_runtime.h>
#include <cuda_fp16.h>
#include <math.h>
#include <cstdint>

#define BATCH 8192
#define EMBED 256
#define HID   256
#define VOCAB 32000

// packed K extents (fp16 2-term: activations duplicated, weights hi|lo)
#define KLOG  512    // logits: 2 x 256
#define KGATE 1536   // gates:  2 x 768

// ============================================================================
// Device scratch (static globals — no runtime allocation)
// ============================================================================
__device__ __half g_Blog[(size_t)VOCAB * KLOG];     // [Wl_hi | Wl_lo]
__device__ __half g_Alog[(size_t)BATCH * KLOG];     // [h16   | h16  ]
__device__ __half g_Bgate[(size_t)1024 * KGATE];    // rows: f,u,o,c  [W_hi | W_lo]
__device__ __half g_Agate[(size_t)BATCH * KGATE];   // [chx16 | chx16]
__device__ float  g_z[(size_t)BATCH * 1024];        // gate pre-activations

// ============================================================================
// PTX helpers (sm_80-era only — safe under .target sm_103)
// ============================================================================
__device__ __forceinline__ uint32_t smem_to_u32(const void* p) {
    uint32_t a;
    asm("{ .reg .u64 t; cvta.to.shared.u64 t, %1; cvt.u32.u64 %0, t; }" : "=r"(a) : "l"(p));
    return a;
}
#define CP_ASYNC16(dst, src) asm volatile("cp.async.cg.shared.global [%0], [%1], 16;" :: "r"(dst), "l"(src) : "memory")
#define CP_COMMIT()  asm volatile("cp.async.commit_group;" ::: "memory")
#define CP_WAIT(N)   asm volatile("cp.async.wait_group %0;" :: "n"(N) : "memory")

#define LDMATRIX_X4(r0, r1, r2, r3, addr) \
    asm volatile("ldmatrix.sync.aligned.m8n8.x4.shared.b16 {%0,%1,%2,%3}, [%4];" \
        : "=r"(r0), "=r"(r1), "=r"(r2), "=r"(r3) : "r"(addr))

#define MMA_F16(d, a, b) \
    asm volatile("mma.sync.aligned.m16n8k16.row.col.f32.f16.f16.f32 " \
        "{%0,%1,%2,%3}, {%4,%5,%6,%7}, {%8,%9}, {%0,%1,%2,%3};" \
        : "+f"((d)[0]), "+f"((d)[1]), "+f"((d)[2]), "+f"((d)[3]) \
        : "r"((a)[0]), "r"((a)[1]), "r"((a)[2]), "r"((a)[3]), \
          "r"((b)[0]), "r"((b)[1]))

// ============================================================================
// Pack kernels
// ============================================================================

// Wl [32000,256] fp32 -> g_Blog rows [hi(256) | lo(256)]
__global__ __launch_bounds__(256) void pack_B_logits(const float* __restrict__ Wl,
                                                     __half* __restrict__ B)
{
    int i = blockIdx.x * 256 + threadIdx.x;          // float4 index
    if (i >= VOCAB * 256 / 4) return;
    int row = i >> 6, c4 = (i & 63) * 4;
    float4 v = ((const float4*)Wl)[i];
    __half h0 = __float2half_rn(v.x), h1 = __float2half_rn(v.y);
    __half h2 = __float2half_rn(v.z), h3 = __float2half_rn(v.w);
    __half l0 = __float2half_rn(v.x - __half2float(h0));
    __half l1 = __float2half_rn(v.y - __half2float(h1));
    __half l2 = __float2half_rn(v.z - __half2float(h2));
    __half l3 = __float2half_rn(v.w - __half2float(h3));
    __half2* dh = (__half2*)(B + (size_t)row * KLOG + c4);
    __half2* dl = (__half2*)(B + (size_t)row * KLOG + 256 + c4);
    dh[0] = __halves2half2(h0, h1); dh[1] = __halves2half2(h2, h3);
    dl[0] = __halves2half2(l0, l1); dl[1] = __halves2half2(l2, l3);
}

// Build gate weight matrix g_Bgate [1024, 1536]:
//   row n: gate g=n>>8, unit j=n&255.  k-space 0..767 = [c_prev | h_prev | x]
//   g<3: W{f,u,o}[j, k] over full 768.  g==3: Wc[j, k-256] for k>=256 else 0.
__global__ __launch_bounds__(256) void pack_B_gates(
    const float* __restrict__ Wf, const float* __restrict__ Wu,
    const float* __restrict__ Wo, const float* __restrict__ Wc,
    __half* __restrict__ B)
{
    int i = blockIdx.x * 256 + threadIdx.x;          // (n, k4) pairs: 1024*192
    if (i >= 1024 * 192) return;
    int n = i / 192, k4 = (i % 192) * 4;
    int g = n >> 8, j = n & 255;
    float4 v;
    if (g == 0)      v = ((const float4*)Wf)[(j * 768 + k4) >> 2];
    else if (g == 1) v = ((const float4*)Wu)[(j * 768 + k4) >> 2];
    else if (g == 2) v = ((const float4*)Wo)[(j * 768 + k4) >> 2];
    else {
        if (k4 < 256) v = make_float4(0.f, 0.f, 0.f, 0.f);
        else          v = ((const float4*)Wc)[(j * 512 + (k4 - 256)) >> 2];
    }
    __half h0 = __float2half_rn(v.x), h1 = __float2half_rn(v.y);
    __half h2 = __float2half_rn(v.z), h3 = __float2half_rn(v.w);
    __half l0 = __float2half_rn(v.x - __half2float(h0));
    __half l1 = __float2half_rn(v.y - __half2float(h1));
    __half l2 = __float2half_rn(v.z - __half2float(h2));
    __half l3 = __float2half_rn(v.w - __half2float(h3));
    __half2* dh = (__half2*)(B + (size_t)n * KGATE + k4);
    __half2* dl = (__half2*)(B + (size_t)n * KGATE + 768 + k4);
    dh[0] = __halves2half2(h0, h1); dh[1] = __halves2half2(h2, h3);
    dl[0] = __halves2half2(l0, l1); dl[1] = __halves2half2(l2, l3);
}

// Build gate activation matrix g_Agate [8192, 1536] = [c,h,x | c,h,x] fp16
__global__ __launch_bounds__(256) void pack_A_gates(
    const float* __restrict__ x, const float* __restrict__ c_prev,
    const float* __restrict__ h_prev, __half* __restrict__ A)
{
    int i = blockIdx.x * 256 + threadIdx.x;          // 8192*192 float4s
    if (i >= BATCH * 192) return;
    int b = i / 192, k4 = (i % 192) * 4;
    float4 v;
    if (k4 < 256)       v = ((const float4*)c_prev)[(b * 256 + k4) >> 2];
    else if (k4 < 512)  v = ((const float4*)h_prev)[(b * 256 + (k4 - 256)) >> 2];
    else                v = ((const float4*)x)[(b * 256 + (k4 - 512)) >> 2];
    __half2 p0 = __halves2half2(__float2half_rn(v.x), __float2half_rn(v.y));
    __half2 p1 = __halves2half2(__float2half_rn(v.z), __float2half_rn(v.w));
    __half2* d0 = (__half2*)(A + (size_t)b * KGATE + k4);
    __half2* d1 = (__half2*)(A + (size_t)b * KGATE + 768 + k4);
    d0[0] = p0; d0[1] = p1;
    d1[0] = p0; d1[1] = p1;
}

// ============================================================================
// Generic fp16 GEMM:  y[M, ldy] tile = A[KTOT] . B[KTOT]^T (+bias)
//   BM=128, BN=256, BK=64, 8 warps (2x4), warp tile 64x64, 3-stage cp.async.
// ============================================================================
#define T_BM 128
#define T_BN 256
#define T_BK 64
#define T_LDS 72                         // halfs per smem row (144B)
#define T_ROWS (T_BM + T_BN)             // 384
#define T_STAGE_B (T_ROWS * T_LDS * 2)   // 55296 bytes
#define T_SMEM (3 * T_STAGE_B)           // 165888 bytes

template<int KTOT, bool BIAS>
__global__ __launch_bounds__(256, 1) void gemm_f16(
    const __half* __restrict__ Ag, const __half* __restrict__ Bg,
    const float* __restrict__ bias, float* __restrict__ y, int ldy)
{
    constexpr int NS = KTOT / T_BK;
    extern __shared__ char smem[];
    const uint32_t sb = smem_to_u32(smem);
    const int tid  = threadIdx.x;
    const int w    = tid >> 5;
    const int lane = tid & 31;
    const int wr   = (w >> 2) * 64;      // 2 row groups
    const int wc   = (w & 3) * 64;       // 4 col groups
    const int m0   = blockIdx.y * T_BM;
    const int n0   = blockIdx.x * T_BN;

    float acc[4][8][4];
    #pragma unroll
    for (int mf = 0; mf < 4; mf++)
        #pragma unroll
        for (int nf = 0; nf < 8; nf++)
            #pragma unroll
            for (int i = 0; i < 4; i++)
                acc[mf][nf][i] = 0.0f;

    auto load_stage = [&](int buf, int k0) {
        uint32_t s0 = sb + buf * T_STAGE_B;
        #pragma unroll
        for (int it = 0; it < 12; it++) {            // 3072 chunks / 256 thr
            int u = it * 256 + tid;
            int r = u >> 3, c8 = u & 7;
            uint32_t so = (uint32_t)(r * T_LDS + c8 * 8) * 2;
            const __half* src = (r < T_BM)
                ? (Ag + (size_t)(m0 + r) * KTOT + k0 + c8 * 8)
                : (Bg + (size_t)(n0 + r - T_BM) * KTOT + k0 + c8 * 8);
            CP_ASYNC16(s0 + so, (const void*)src);
        }
    };

    load_stage(0, 0);        CP_COMMIT();
    load_stage(1, T_BK);     CP_COMMIT();

    for (int s = 0; s < NS; s++) {
        if (s + 2 < NS) { load_stage((s + 2) % 3, (s + 2) * T_BK); CP_COMMIT(); }
        if (s < NS - 2)       CP_WAIT(2);
        else if (s == NS - 2) CP_WAIT(1);
        else                  CP_WAIT(0);
        __syncthreads();

        const uint32_t sA = sb + (s % 3) * T_STAGE_B;
        const uint32_t sB = sA + T_BM * T_LDS * 2;

        #pragma unroll
        for (int ks = 0; ks < 4; ks++) {
            uint32_t a[4][4];
            {
                int kh = ks * 16 + (lane >> 4) * 8;
                #pragma unroll
                for (int mf = 0; mf < 4; mf++) {
                    int row = wr + mf * 16 + (lane & 15);
                    uint32_t ad = sA + (uint32_t)(row * T_LDS + kh) * 2;
                    LDMATRIX_X4(a[mf][0], a[mf][1], a[mf][2], a[mf][3], ad);
                }
            }
            uint32_t b[8][2];
            {
                int kb = ks * 16 + ((lane >> 3) & 1) * 8;
                #pragma unroll
                for (int p = 0; p < 4; p++) {
                    int n = wc + p * 16 + (lane & 7) + ((lane >> 4) & 1) * 8;
                    uint32_t ad = sB + (uint32_t)(n * T_LDS + kb) * 2;
                    LDMATRIX_X4(b[2 * p][0], b[2 * p][1], b[2 * p + 1][0], b[2 * p + 1][1], ad);
                }
            }
            #pragma unroll
            for (int mf = 0; mf < 4; mf++)
                #pragma unroll
                for (int nf = 0; nf < 8; nf++)
                    MMA_F16(acc[mf][nf], a[mf], b[nf]);
        }
        __syncthreads();
    }

    // epilogue
    #pragma unroll
    for (int mf = 0; mf < 4; mf++) {
        int r0 = m0 + wr + mf * 16 + (lane >> 2);
        #pragma unroll
        for (int nf = 0; nf < 8; nf++) {
            int c = n0 + wc + nf * 8 + (lane & 3) * 2;
            float2 bv = BIAS ? *(const float2*)(bias + c) : make_float2(0.f, 0.f);
            float2 v0 = make_float2(acc[mf][nf][0] + bv.x, acc[mf][nf][1] + bv.y);
            float2 v1 = make_float2(acc[mf][nf][2] + bv.x, acc[mf][nf][3] + bv.y);
            *(float2*)(y + (size_t)r0 * ldy + c)       = v0;
            *(float2*)(y + (size_t)(r0 + 8) * ldy + c) = v1;
        }
    }
}

// ============================================================================
// Gate combine: z[8192,1024] -> c_t, h_t  (+ logits A operand, duplicated fp16)
// ============================================================================
__global__ __launch_bounds__(256) void gate_combine(
    const float* __restrict__ z, const float* __restrict__ c_prev,
    const float* __restrict__ bf, const float* __restrict__ bu,
    const float* __restrict__ bo, const float* __restrict__ bc,
    float* __restrict__ c_out, float* __restrict__ h_out,
    __half* __restrict__ Alog)
{
    int i = blockIdx.x * 256 + threadIdx.x;     // 8192*64 float4 slots
    if (i >= BATCH * 64) return;
    int b = i >> 6, j = (i & 63) * 4;
    const float4 zf = *(const float4*)(z + (size_t)b * 1024 + j);
    const float4 zu = *(const float4*)(z + (size_t)b * 1024 + 256 + j);
    const float4 zo = *(const float4*)(z + (size_t)b * 1024 + 512 + j);
    const float4 zc = *(const float4*)(z + (size_t)b * 1024 + 768 + j);
    const float4 cp = *(const float4*)(c_prev + (size_t)b * 256 + j);
    const float4 vbf = *(const float4*)(bf + j);
    const float4 vbu = *(const float4*)(bu + j);
    const float4 vbo = *(const float4*)(bo + j);
    const float4 vbc = *(const float4*)(bc + j);

    float ct[4], ht[4];
    #pragma unroll
    for (int e = 0; e < 4; e++) {
        float f = 1.0f / (1.0f + expf(-(((const float*)&zf)[e] + ((const float*)&vbf)[e])));
        float u = 1.0f / (1.0f + expf(-(((const float*)&zu)[e] + ((const float*)&vbu)[e])));
        float o = 1.0f / (1.0f + expf(-(((const float*)&zo)[e] + ((const float*)&vbo)[e])));
        float cn = tanhf(((const float*)&zc)[e] + ((const float*)&vbc)[e]);
        float c = f * ((const float*)&cp)[e] + u * cn;
        ct[e] = c;
        ht[e] = o * tanhf(c);
    }
    *(float4*)(c_out + (size_t)b * 256 + j) = make_float4(ct[0], ct[1], ct[2], ct[3]);
    *(float4*)(h_out + (size_t)b * 256 + j) = make_float4(ht[0], ht[1], ht[2], ht[3]);

    __half2 p0 = __halves2half2(__float2half_rn(ht[0]), __float2half_rn(ht[1]));
    __half2 p1 = __halves2half2(__float2half_rn(ht[2]), __float2half_rn(ht[3]));
    __half2* d0 = (__half2*)(Alog + (size_t)b * KLOG + j);
    __half2* d1 = (__half2*)(Alog + (size_t)b * KLOG + 256 + j);
    d0[0] = p0; d0[1] = p1;
    d1[0] = p0; d1[1] = p1;
}

// ============================================================================
// Launch
// ============================================================================
extern "C" void kernel_launch(void* const* d_in, const int* in_sizes, int n_in,
                              void* d_out, int out_size)
{
    const float* x      = (const float*)d_in[0];
    const float* c_prev = (const float*)d_in[1];
    const float* h_prev = (const float*)d_in[2];
    const float* Wf     = (const float*)d_in[3];
    const float* bf     = (const float*)d_in[4];
    const float* Wu     = (const float*)d_in[5];
    const float* bu     = (const float*)d_in[6];
    const float* Wo     = (const float*)d_in[7];
    const float* bo     = (const float*)d_in[8];
    const float* Wc     = (const float*)d_in[9];
    const float* bc     = (const float*)d_in[10];
    const float* Wl     = (const float*)d_in[11];
    const float* bl     = (const float*)d_in[12];

    float* out   = (float*)d_out;
    float* c_out = out;
    float* h_out = out + (size_t)BATCH * HID;
    float* y_out = out + (size_t)2 * BATCH * HID;

    __half *blog, *alog, *bgate, *agate; float* zbuf;
    cudaGetSymbolAddress((void**)&blog,  g_Blog);
    cudaGetSymbolAddress((void**)&alog,  g_Alog);
    cudaGetSymbolAddress((void**)&bgate, g_Bgate);
    cudaGetSymbolAddress((void**)&agate, g_Agate);
    cudaGetSymbolAddress((void**)&zbuf,  g_z);

    cudaFuncSetAttribute(gemm_f16<KGATE, false>,
                         cudaFuncAttributeMaxDynamicSharedMemorySize, T_SMEM);
    cudaFuncSetAttribute(gemm_f16<KLOG, true>,
                         cudaFuncAttributeMaxDynamicSharedMemorySize, T_SMEM);

    // 1) packs
    pack_B_gates<<<(1024 * 192 + 255) / 256, 256>>>(Wf, Wu, Wo, Wc, bgate);
    pack_A_gates<<<(BATCH * 192 + 255) / 256, 256>>>(x, c_prev, h_prev, agate);
    pack_B_logits<<<(VOCAB * 64 + 255) / 256, 256>>>(Wl, blog);

    // 2) gates GEMM: z = Agate . Bgate^T   [8192, 1024]
    {
        dim3 g(1024 / T_BN, BATCH / T_BM);   // (4, 64)
        gemm_f16<KGATE, false><<<g, 256, T_SMEM>>>(agate, bgate, nullptr, zbuf, 1024);
    }
    // 3) combine -> c_t, h_t, Alog
    gate_combine<<<(BATCH * 64 + 255) / 256, 256>>>(zbuf, c_prev, bf, bu, bo, bc,
                                                    c_out, h_out, alog);
    // 4) logits GEMM: y = Alog . Blog^T + bl   [8192, 32000]
    {
        dim3 g(VOCAB / T_BN, BATCH / T_BM);  // (125, 64)
        gemm_f16<KLOG, true><<<g, 256, T_SMEM>>>(alog, blog, bl, y_out, VOCAB);
    }
}

// round 5
// speedup vs baseline: 8.5681x; 1.6634x over previous
#include <cuda_runtime.h>
#include <cuda_fp16.h>
#include <math.h>
#include <cstdint>

#define BATCH 8192
#define EMBED 256
#define HID   256
#define VOCAB 32000

#define KLOG  256    // logits K (single fp16)
#define KGATE 768    // gates K  (single fp16, [c_prev|h_prev|x])

// ============================================================================
// Device scratch (static globals — no runtime allocation)
// ============================================================================
__device__ __half g_Blog[(size_t)VOCAB * KLOG];     // Wl fp16
__device__ __half g_Alog[(size_t)BATCH * KLOG];     // h_t fp16
__device__ __half g_Bgate[(size_t)1024 * KGATE];    // rows: f,u,o,c
__device__ __half g_Agate[(size_t)BATCH * KGATE];   // [c,h,x] fp16
__device__ float  g_z[(size_t)BATCH * 1024];        // gate pre-activations

// ============================================================================
// PTX helpers (sm_80-era only — safe under .target sm_103)
// ============================================================================
__device__ __forceinline__ uint32_t smem_to_u32(const void* p) {
    uint32_t a;
    asm("{ .reg .u64 t; cvta.to.shared.u64 t, %1; cvt.u32.u64 %0, t; }" : "=r"(a) : "l"(p));
    return a;
}
#define CP_ASYNC16(dst, src) asm volatile("cp.async.cg.shared.global [%0], [%1], 16;" :: "r"(dst), "l"(src) : "memory")
#define CP_COMMIT()  asm volatile("cp.async.commit_group;" ::: "memory")
#define CP_WAIT(N)   asm volatile("cp.async.wait_group %0;" :: "n"(N) : "memory")

#define LDMATRIX_X4(r0, r1, r2, r3, addr) \
    asm volatile("ldmatrix.sync.aligned.m8n8.x4.shared.b16 {%0,%1,%2,%3}, [%4];" \
        : "=r"(r0), "=r"(r1), "=r"(r2), "=r"(r3) : "r"(addr))

#define MMA_F16(d, a, b) \
    asm volatile("mma.sync.aligned.m16n8k16.row.col.f32.f16.f16.f32 " \
        "{%0,%1,%2,%3}, {%4,%5,%6,%7}, {%8,%9}, {%0,%1,%2,%3};" \
        : "+f"((d)[0]), "+f"((d)[1]), "+f"((d)[2]), "+f"((d)[3]) \
        : "r"((a)[0]), "r"((a)[1]), "r"((a)[2]), "r"((a)[3]), \
          "r"((b)[0]), "r"((b)[1]))

// ============================================================================
// Pack kernels (plain fp32 -> fp16 conversion)
// ============================================================================

// Wl [32000,256] fp32 -> fp16
__global__ __launch_bounds__(256) void pack_B_logits(const float* __restrict__ Wl,
                                                     __half* __restrict__ B)
{
    int i = blockIdx.x * 256 + threadIdx.x;          // float4 index
    if (i >= VOCAB * 256 / 4) return;
    float4 v = ((const float4*)Wl)[i];
    __half2 p0 = __halves2half2(__float2half_rn(v.x), __float2half_rn(v.y));
    __half2 p1 = __halves2half2(__float2half_rn(v.z), __float2half_rn(v.w));
    ((__half2*)B)[i * 2]     = p0;
    ((__half2*)B)[i * 2 + 1] = p1;
}

// Gate weight matrix g_Bgate [1024, 768]:
//   row n: gate g=n>>8, unit j=n&255.  k-space 0..767 = [c_prev | h_prev | x]
//   g<3: W{f,u,o}[j, k].  g==3: Wc[j, k-256] for k>=256, else 0.
__global__ __launch_bounds__(256) void pack_B_gates(
    const float* __restrict__ Wf, const float* __restrict__ Wu,
    const float* __restrict__ Wo, const float* __restrict__ Wc,
    __half* __restrict__ B)
{
    int i = blockIdx.x * 256 + threadIdx.x;          // 1024*192 float4 slots
    if (i >= 1024 * 192) return;
    int n = i / 192, k4 = (i % 192) * 4;
    int g = n >> 8, j = n & 255;
    float4 v;
    if (g == 0)      v = ((const float4*)Wf)[(j * 768 + k4) >> 2];
    else if (g == 1) v = ((const float4*)Wu)[(j * 768 + k4) >> 2];
    else if (g == 2) v = ((const float4*)Wo)[(j * 768 + k4) >> 2];
    else {
        if (k4 < 256) v = make_float4(0.f, 0.f, 0.f, 0.f);
        else          v = ((const float4*)Wc)[(j * 512 + (k4 - 256)) >> 2];
    }
    __half2 p0 = __halves2half2(__float2half_rn(v.x), __float2half_rn(v.y));
    __half2 p1 = __halves2half2(__float2half_rn(v.z), __float2half_rn(v.w));
    __half2* d = (__half2*)(B + (size_t)n * KGATE + k4);
    d[0] = p0; d[1] = p1;
}

// Gate activation matrix g_Agate [8192, 768] = [c_prev, h_prev, x] fp16
__global__ __launch_bounds__(256) void pack_A_gates(
    const float* __restrict__ x, const float* __restrict__ c_prev,
    const float* __restrict__ h_prev, __half* __restrict__ A)
{
    int i = blockIdx.x * 256 + threadIdx.x;          // 8192*192 float4 slots
    if (i >= BATCH * 192) return;
    int b = i / 192, k4 = (i % 192) * 4;
    float4 v;
    if (k4 < 256)       v = ((const float4*)c_prev)[(b * 256 + k4) >> 2];
    else if (k4 < 512)  v = ((const float4*)h_prev)[(b * 256 + (k4 - 256)) >> 2];
    else                v = ((const float4*)x)[(b * 256 + (k4 - 512)) >> 2];
    __half2 p0 = __halves2half2(__float2half_rn(v.x), __float2half_rn(v.y));
    __half2 p1 = __halves2half2(__float2half_rn(v.z), __float2half_rn(v.w));
    __half2* d = (__half2*)(A + (size_t)b * KGATE + k4);
    d[0] = p0; d[1] = p1;
}

// ============================================================================
// Generic fp16 GEMM:  y[M, ldy] tile = A[KTOT] . B[KTOT]^T (+bias)
//   BM=128, BN=256, BK=64, 8 warps (2x4), warp tile 64x64, 3-stage cp.async.
// ============================================================================
#define T_BM 128
#define T_BN 256
#define T_BK 64
#define T_LDS 72                         // halfs per smem row (144B)
#define T_ROWS (T_BM + T_BN)             // 384
#define T_STAGE_B (T_ROWS * T_LDS * 2)   // 55296 bytes
#define T_SMEM (3 * T_STAGE_B)           // 165888 bytes

template<int KTOT, bool BIAS>
__global__ __launch_bounds__(256, 1) void gemm_f16(
    const __half* __restrict__ Ag, const __half* __restrict__ Bg,
    const float* __restrict__ bias, float* __restrict__ y, int ldy)
{
    constexpr int NS = KTOT / T_BK;
    extern __shared__ char smem[];
    const uint32_t sb = smem_to_u32(smem);
    const int tid  = threadIdx.x;
    const int w    = tid >> 5;
    const int lane = tid & 31;
    const int wr   = (w >> 2) * 64;      // 2 row groups
    const int wc   = (w & 3) * 64;       // 4 col groups
    const int m0   = blockIdx.y * T_BM;
    const int n0   = blockIdx.x * T_BN;

    float acc[4][8][4];
    #pragma unroll
    for (int mf = 0; mf < 4; mf++)
        #pragma unroll
        for (int nf = 0; nf < 8; nf++)
            #pragma unroll
            for (int i = 0; i < 4; i++)
                acc[mf][nf][i] = 0.0f;

    auto load_stage = [&](int buf, int k0) {
        uint32_t s0 = sb + buf * T_STAGE_B;
        #pragma unroll
        for (int it = 0; it < 12; it++) {            // 3072 chunks / 256 thr
            int u = it * 256 + tid;
            int r = u >> 3, c8 = u & 7;
            uint32_t so = (uint32_t)(r * T_LDS + c8 * 8) * 2;
            const __half* src = (r < T_BM)
                ? (Ag + (size_t)(m0 + r) * KTOT + k0 + c8 * 8)
                : (Bg + (size_t)(n0 + r - T_BM) * KTOT + k0 + c8 * 8);
            CP_ASYNC16(s0 + so, (const void*)src);
        }
    };

    load_stage(0, 0);        CP_COMMIT();
    load_stage(1, T_BK);     CP_COMMIT();

    for (int s = 0; s < NS; s++) {
        if (s + 2 < NS) { load_stage((s + 2) % 3, (s + 2) * T_BK); CP_COMMIT(); }
        if (s < NS - 2)       CP_WAIT(2);
        else if (s == NS - 2) CP_WAIT(1);
        else                  CP_WAIT(0);
        __syncthreads();

        const uint32_t sA = sb + (s % 3) * T_STAGE_B;
        const uint32_t sB = sA + T_BM * T_LDS * 2;

        #pragma unroll
        for (int ks = 0; ks < 4; ks++) {
            uint32_t a[4][4];
            {
                int kh = ks * 16 + (lane >> 4) * 8;
                #pragma unroll
                for (int mf = 0; mf < 4; mf++) {
                    int row = wr + mf * 16 + (lane & 15);
                    uint32_t ad = sA + (uint32_t)(row * T_LDS + kh) * 2;
                    LDMATRIX_X4(a[mf][0], a[mf][1], a[mf][2], a[mf][3], ad);
                }
            }
            uint32_t b[8][2];
            {
                int kb = ks * 16 + ((lane >> 3) & 1) * 8;
                #pragma unroll
                for (int p = 0; p < 4; p++) {
                    int n = wc + p * 16 + (lane & 7) + ((lane >> 4) & 1) * 8;
                    uint32_t ad = sB + (uint32_t)(n * T_LDS + kb) * 2;
                    LDMATRIX_X4(b[2 * p][0], b[2 * p][1], b[2 * p + 1][0], b[2 * p + 1][1], ad);
                }
            }
            #pragma unroll
            for (int mf = 0; mf < 4; mf++)
                #pragma unroll
                for (int nf = 0; nf < 8; nf++)
                    MMA_F16(acc[mf][nf], a[mf], b[nf]);
        }
        __syncthreads();
    }

    // epilogue
    #pragma unroll
    for (int mf = 0; mf < 4; mf++) {
        int r0 = m0 + wr + mf * 16 + (lane >> 2);
        #pragma unroll
        for (int nf = 0; nf < 8; nf++) {
            int c = n0 + wc + nf * 8 + (lane & 3) * 2;
            float2 bv = BIAS ? *(const float2*)(bias + c) : make_float2(0.f, 0.f);
            float2 v0 = make_float2(acc[mf][nf][0] + bv.x, acc[mf][nf][1] + bv.y);
            float2 v1 = make_float2(acc[mf][nf][2] + bv.x, acc[mf][nf][3] + bv.y);
            *(float2*)(y + (size_t)r0 * ldy + c)       = v0;
            *(float2*)(y + (size_t)(r0 + 8) * ldy + c) = v1;
        }
    }
}

// ============================================================================
// Gate combine: z[8192,1024] -> c_t, h_t (+ fp16 logits A operand)
// ============================================================================
__global__ __launch_bounds__(256) void gate_combine(
    const float* __restrict__ z, const float* __restrict__ c_prev,
    const float* __restrict__ bf, const float* __restrict__ bu,
    const float* __restrict__ bo, const float* __restrict__ bc,
    float* __restrict__ c_out, float* __restrict__ h_out,
    __half* __restrict__ Alog)
{
    int i = blockIdx.x * 256 + threadIdx.x;     // 8192*64 float4 slots
    if (i >= BATCH * 64) return;
    int b = i >> 6, j = (i & 63) * 4;
    const float4 zf = *(const float4*)(z + (size_t)b * 1024 + j);
    const float4 zu = *(const float4*)(z + (size_t)b * 1024 + 256 + j);
    const float4 zo = *(const float4*)(z + (size_t)b * 1024 + 512 + j);
    const float4 zc = *(const float4*)(z + (size_t)b * 1024 + 768 + j);
    const float4 cp = *(const float4*)(c_prev + (size_t)b * 256 + j);
    const float4 vbf = *(const float4*)(bf + j);
    const float4 vbu = *(const float4*)(bu + j);
    const float4 vbo = *(const float4*)(bo + j);
    const float4 vbc = *(const float4*)(bc + j);

    float ct[4], ht[4];
    #pragma unroll
    for (int e = 0; e < 4; e++) {
        float f = 1.0f / (1.0f + expf(-(((const float*)&zf)[e] + ((const float*)&vbf)[e])));
        float u = 1.0f / (1.0f + expf(-(((const float*)&zu)[e] + ((const float*)&vbu)[e])));
        float o = 1.0f / (1.0f + expf(-(((const float*)&zo)[e] + ((const float*)&vbo)[e])));
        float cn = tanhf(((const float*)&zc)[e] + ((const float*)&vbc)[e]);
        float c = f * ((const float*)&cp)[e] + u * cn;
        ct[e] = c;
        ht[e] = o * tanhf(c);
    }
    *(float4*)(c_out + (size_t)b * 256 + j) = make_float4(ct[0], ct[1], ct[2], ct[3]);
    *(float4*)(h_out + (size_t)b * 256 + j) = make_float4(ht[0], ht[1], ht[2], ht[3]);

    __half2 p0 = __halves2half2(__float2half_rn(ht[0]), __float2half_rn(ht[1]));
    __half2 p1 = __halves2half2(__float2half_rn(ht[2]), __float2half_rn(ht[3]));
    __half2* d = (__half2*)(Alog + (size_t)b * KLOG + j);
    d[0] = p0; d[1] = p1;
}

// ============================================================================
// Launch
// ============================================================================
extern "C" void kernel_launch(void* const* d_in, const int* in_sizes, int n_in,
                              void* d_out, int out_size)
{
    const float* x      = (const float*)d_in[0];
    const float* c_prev = (const float*)d_in[1];
    const float* h_prev = (const float*)d_in[2];
    const float* Wf     = (const float*)d_in[3];
    const float* bf     = (const float*)d_in[4];
    const float* Wu     = (const float*)d_in[5];
    const float* bu     = (const float*)d_in[6];
    const float* Wo     = (const float*)d_in[7];
    const float* bo     = (const float*)d_in[8];
    const float* Wc     = (const float*)d_in[9];
    const float* bc     = (const float*)d_in[10];
    const float* Wl     = (const float*)d_in[11];
    const float* bl     = (const float*)d_in[12];

    float* out   = (float*)d_out;
    float* c_out = out;
    float* h_out = out + (size_t)BATCH * HID;
    float* y_out = out + (size_t)2 * BATCH * HID;

    __half *blog, *alog, *bgate, *agate; float* zbuf;
    cudaGetSymbolAddress((void**)&blog,  g_Blog);
    cudaGetSymbolAddress((void**)&alog,  g_Alog);
    cudaGetSymbolAddress((void**)&bgate, g_Bgate);
    cudaGetSymbolAddress((void**)&agate, g_Agate);
    cudaGetSymbolAddress((void**)&zbuf,  g_z);

    cudaFuncSetAttribute(gemm_f16<KGATE, false>,
                         cudaFuncAttributeMaxDynamicSharedMemorySize, T_SMEM);
    cudaFuncSetAttribute(gemm_f16<KLOG, true>,
                         cudaFuncAttributeMaxDynamicSharedMemorySize, T_SMEM);

    // 1) packs
    pack_B_gates<<<(1024 * 192 + 255) / 256, 256>>>(Wf, Wu, Wo, Wc, bgate);
    pack_A_gates<<<(BATCH * 192 + 255) / 256, 256>>>(x, c_prev, h_prev, agate);
    pack_B_logits<<<(VOCAB * 64 + 255) / 256, 256>>>(Wl, blog);

    // 2) gates GEMM: z = Agate . Bgate^T   [8192, 1024]
    {
        dim3 g(1024 / T_BN, BATCH / T_BM);   // (4, 64)
        gemm_f16<KGATE, false><<<g, 256, T_SMEM>>>(agate, bgate, nullptr, zbuf, 1024);
    }
    // 3) combine -> c_t, h_t, Alog
    gate_combine<<<(BATCH * 64 + 255) / 256, 256>>>(zbuf, c_prev, bf, bu, bo, bc,
                                                    c_out, h_out, alog);
    // 4) logits GEMM: y = Alog . Blog^T + bl   [8192, 32000]
    {
        dim3 g(VOCAB / T_BN, BATCH / T_BM);  // (125, 64)
        gemm_f16<KLOG, true><<<g, 256, T_SMEM>>>(alog, blog, bl, y_out, VOCAB);
    }
}

// round 6
// speedup vs baseline: 8.9128x; 1.0402x over previous
#include <cuda_runtime.h>
#include <cuda_fp16.h>
#include <math.h>
#include <cstdint>

#define BATCH 8192
#define EMBED 256
#define HID   256
#define VOCAB 32000

#define KLOG  256    // logits K (single fp16)
#define KGATE 768    // gates K  (single fp16, [c_prev|h_prev|x])

// ============================================================================
// Device scratch (static globals — no runtime allocation)
// ============================================================================
__device__ __half g_Blog[(size_t)VOCAB * KLOG];     // Wl fp16
__device__ __half g_Alog[(size_t)BATCH * KLOG];     // h_t fp16
__device__ __half g_Bgate[(size_t)1024 * KGATE];    // rows: f,u,o,c
__device__ __half g_Agate[(size_t)BATCH * KGATE];   // [c,h,x] fp16
__device__ float  g_z[(size_t)BATCH * 1024];        // gate pre-activations

// ============================================================================
// PTX helpers (sm_80-era only — safe under .target sm_103)
// ============================================================================
__device__ __forceinline__ uint32_t smem_to_u32(const void* p) {
    uint32_t a;
    asm("{ .reg .u64 t; cvta.to.shared.u64 t, %1; cvt.u32.u64 %0, t; }" : "=r"(a) : "l"(p));
    return a;
}
#define CP_ASYNC16(dst, src) asm volatile("cp.async.cg.shared.global [%0], [%1], 16;" :: "r"(dst), "l"(src) : "memory")
#define CP_COMMIT()  asm volatile("cp.async.commit_group;" ::: "memory")
#define CP_WAIT(N)   asm volatile("cp.async.wait_group %0;" :: "n"(N) : "memory")

#define LDMATRIX_X4(r0, r1, r2, r3, addr) \
    asm volatile("ldmatrix.sync.aligned.m8n8.x4.shared.b16 {%0,%1,%2,%3}, [%4];" \
        : "=r"(r0), "=r"(r1), "=r"(r2), "=r"(r3) : "r"(addr))

#define MMA_F16(d, a, b) \
    asm volatile("mma.sync.aligned.m16n8k16.row.col.f32.f16.f16.f32 " \
        "{%0,%1,%2,%3}, {%4,%5,%6,%7}, {%8,%9}, {%0,%1,%2,%3};" \
        : "+f"((d)[0]), "+f"((d)[1]), "+f"((d)[2]), "+f"((d)[3]) \
        : "r"((a)[0]), "r"((a)[1]), "r"((a)[2]), "r"((a)[3]), \
          "r"((b)[0]), "r"((b)[1]))

// ============================================================================
// Pack kernels (plain fp32 -> fp16 conversion)
// ============================================================================

// Wl [32000,256] fp32 -> fp16
__global__ __launch_bounds__(256) void pack_B_logits(const float* __restrict__ Wl,
                                                     __half* __restrict__ B)
{
    int i = blockIdx.x * 256 + threadIdx.x;          // float4 index
    if (i >= VOCAB * 256 / 4) return;
    float4 v = ((const float4*)Wl)[i];
    __half2 p0 = __halves2half2(__float2half_rn(v.x), __float2half_rn(v.y));
    __half2 p1 = __halves2half2(__float2half_rn(v.z), __float2half_rn(v.w));
    ((__half2*)B)[i * 2]     = p0;
    ((__half2*)B)[i * 2 + 1] = p1;
}

// Gate weight matrix g_Bgate [1024, 768]:
//   row n: gate g=n>>8, unit j=n&255.  k-space 0..767 = [c_prev | h_prev | x]
//   g<3: W{f,u,o}[j, k].  g==3: Wc[j, k-256] for k>=256, else 0.
__global__ __launch_bounds__(256) void pack_B_gates(
    const float* __restrict__ Wf, const float* __restrict__ Wu,
    const float* __restrict__ Wo, const float* __restrict__ Wc,
    __half* __restrict__ B)
{
    int i = blockIdx.x * 256 + threadIdx.x;          // 1024*192 float4 slots
    if (i >= 1024 * 192) return;
    int n = i / 192, k4 = (i % 192) * 4;
    int g = n >> 8, j = n & 255;
    float4 v;
    if (g == 0)      v = ((const float4*)Wf)[(j * 768 + k4) >> 2];
    else if (g == 1) v = ((const float4*)Wu)[(j * 768 + k4) >> 2];
    else if (g == 2) v = ((const float4*)Wo)[(j * 768 + k4) >> 2];
    else {
        if (k4 < 256) v = make_float4(0.f, 0.f, 0.f, 0.f);
        else          v = ((const float4*)Wc)[(j * 512 + (k4 - 256)) >> 2];
    }
    __half2 p0 = __halves2half2(__float2half_rn(v.x), __float2half_rn(v.y));
    __half2 p1 = __halves2half2(__float2half_rn(v.z), __float2half_rn(v.w));
    __half2* d = (__half2*)(B + (size_t)n * KGATE + k4);
    d[0] = p0; d[1] = p1;
}

// Gate activation matrix g_Agate [8192, 768] = [c_prev, h_prev, x] fp16
__global__ __launch_bounds__(256) void pack_A_gates(
    const float* __restrict__ x, const float* __restrict__ c_prev,
    const float* __restrict__ h_prev, __half* __restrict__ A)
{
    int i = blockIdx.x * 256 + threadIdx.x;          // 8192*192 float4 slots
    if (i >= BATCH * 192) return;
    int b = i / 192, k4 = (i % 192) * 4;
    float4 v;
    if (k4 < 256)       v = ((const float4*)c_prev)[(b * 256 + k4) >> 2];
    else if (k4 < 512)  v = ((const float4*)h_prev)[(b * 256 + (k4 - 256)) >> 2];
    else                v = ((const float4*)x)[(b * 256 + (k4 - 512)) >> 2];
    __half2 p0 = __halves2half2(__float2half_rn(v.x), __float2half_rn(v.y));
    __half2 p1 = __halves2half2(__float2half_rn(v.z), __float2half_rn(v.w));
    __half2* d = (__half2*)(A + (size_t)b * KGATE + k4);
    d[0] = p0; d[1] = p1;
}

// ============================================================================
// Generic fp16 GEMM:  y[M, ldy] tile = A[KTOT] . B[KTOT]^T (+bias)
//   BM=128, BN=256, BK=64, 16 warps (4x4), warp tile 32x64, 3-stage cp.async.
// ============================================================================
#define T_BM 128
#define T_BN 256
#define T_BK 64
#define T_THREADS 512
#define T_LDS 72                         // halfs per smem row (144B)
#define T_ROWS (T_BM + T_BN)             // 384
#define T_STAGE_B (T_ROWS * T_LDS * 2)   // 55296 bytes
#define T_SMEM (3 * T_STAGE_B)           // 165888 bytes

template<int KTOT, bool BIAS>
__global__ __launch_bounds__(T_THREADS, 1) void gemm_f16(
    const __half* __restrict__ Ag, const __half* __restrict__ Bg,
    const float* __restrict__ bias, float* __restrict__ y, int ldy)
{
    constexpr int NS = KTOT / T_BK;
    extern __shared__ char smem[];
    const uint32_t sb = smem_to_u32(smem);
    const int tid  = threadIdx.x;
    const int w    = tid >> 5;
    const int lane = tid & 31;
    const int wr   = (w >> 2) * 32;      // 4 row groups of 32
    const int wc   = (w & 3) * 64;       // 4 col groups of 64
    const int m0   = blockIdx.y * T_BM;
    const int n0   = blockIdx.x * T_BN;

    float acc[2][8][4];
    #pragma unroll
    for (int mf = 0; mf < 2; mf++)
        #pragma unroll
        for (int nf = 0; nf < 8; nf++)
            #pragma unroll
            for (int i = 0; i < 4; i++)
                acc[mf][nf][i] = 0.0f;

    auto load_stage = [&](int buf, int k0) {
        uint32_t s0 = sb + buf * T_STAGE_B;
        #pragma unroll
        for (int it = 0; it < 6; it++) {             // 3072 chunks / 512 thr
            int u = it * T_THREADS + tid;
            int r = u >> 3, c8 = u & 7;
            uint32_t so = (uint32_t)(r * T_LDS + c8 * 8) * 2;
            const __half* src = (r < T_BM)
                ? (Ag + (size_t)(m0 + r) * KTOT + k0 + c8 * 8)
                : (Bg + (size_t)(n0 + r - T_BM) * KTOT + k0 + c8 * 8);
            CP_ASYNC16(s0 + so, (const void*)src);
        }
    };

    load_stage(0, 0);        CP_COMMIT();
    load_stage(1, T_BK);     CP_COMMIT();

    for (int s = 0; s < NS; s++) {
        if (s + 2 < NS) { load_stage((s + 2) % 3, (s + 2) * T_BK); CP_COMMIT(); }
        if (s < NS - 2)       CP_WAIT(2);
        else if (s == NS - 2) CP_WAIT(1);
        else                  CP_WAIT(0);
        __syncthreads();

        const uint32_t sA = sb + (s % 3) * T_STAGE_B;
        const uint32_t sB = sA + T_BM * T_LDS * 2;

        #pragma unroll
        for (int ks = 0; ks < 4; ks++) {
            uint32_t a[2][4];
            {
                int kh = ks * 16 + (lane >> 4) * 8;
                #pragma unroll
                for (int mf = 0; mf < 2; mf++) {
                    int row = wr + mf * 16 + (lane & 15);
                    uint32_t ad = sA + (uint32_t)(row * T_LDS + kh) * 2;
                    LDMATRIX_X4(a[mf][0], a[mf][1], a[mf][2], a[mf][3], ad);
                }
            }
            uint32_t b[8][2];
            {
                int kb = ks * 16 + ((lane >> 3) & 1) * 8;
                #pragma unroll
                for (int p = 0; p < 4; p++) {
                    int n = wc + p * 16 + (lane & 7) + ((lane >> 4) & 1) * 8;
                    uint32_t ad = sB + (uint32_t)(n * T_LDS + kb) * 2;
                    LDMATRIX_X4(b[2 * p][0], b[2 * p][1], b[2 * p + 1][0], b[2 * p + 1][1], ad);
                }
            }
            #pragma unroll
            for (int mf = 0; mf < 2; mf++)
                #pragma unroll
                for (int nf = 0; nf < 8; nf++)
                    MMA_F16(acc[mf][nf], a[mf], b[nf]);
        }
        __syncthreads();
    }

    // epilogue
    #pragma unroll
    for (int mf = 0; mf < 2; mf++) {
        int r0 = m0 + wr + mf * 16 + (lane >> 2);
        #pragma unroll
        for (int nf = 0; nf < 8; nf++) {
            int c = n0 + wc + nf * 8 + (lane & 3) * 2;
            float2 bv = BIAS ? *(const float2*)(bias + c) : make_float2(0.f, 0.f);
            float2 v0 = make_float2(acc[mf][nf][0] + bv.x, acc[mf][nf][1] + bv.y);
            float2 v1 = make_float2(acc[mf][nf][2] + bv.x, acc[mf][nf][3] + bv.y);
            *(float2*)(y + (size_t)r0 * ldy + c)       = v0;
            *(float2*)(y + (size_t)(r0 + 8) * ldy + c) = v1;
        }
    }
}

// ============================================================================
// Gate combine: z[8192,1024] -> c_t, h_t (+ fp16 logits A operand)
// ============================================================================
__global__ __launch_bounds__(256) void gate_combine(
    const float* __restrict__ z, const float* __restrict__ c_prev,
    const float* __restrict__ bf, const float* __restrict__ bu,
    const float* __restrict__ bo, const float* __restrict__ bc,
    float* __restrict__ c_out, float* __restrict__ h_out,
    __half* __restrict__ Alog)
{
    int i = blockIdx.x * 256 + threadIdx.x;     // 8192*64 float4 slots
    if (i >= BATCH * 64) return;
    int b = i >> 6, j = (i & 63) * 4;
    const float4 zf = *(const float4*)(z + (size_t)b * 1024 + j);
    const float4 zu = *(const float4*)(z + (size_t)b * 1024 + 256 + j);
    const float4 zo = *(const float4*)(z + (size_t)b * 1024 + 512 + j);
    const float4 zc = *(const float4*)(z + (size_t)b * 1024 + 768 + j);
    const float4 cp = *(const float4*)(c_prev + (size_t)b * 256 + j);
    const float4 vbf = *(const float4*)(bf + j);
    const float4 vbu = *(const float4*)(bu + j);
    const float4 vbo = *(const float4*)(bo + j);
    const float4 vbc = *(const float4*)(bc + j);

    float ct[4], ht[4];
    #pragma unroll
    for (int e = 0; e < 4; e++) {
        float f = 1.0f / (1.0f + expf(-(((const float*)&zf)[e] + ((const float*)&vbf)[e])));
        float u = 1.0f / (1.0f + expf(-(((const float*)&zu)[e] + ((const float*)&vbu)[e])));
        float o = 1.0f / (1.0f + expf(-(((const float*)&zo)[e] + ((const float*)&vbo)[e])));
        float cn = tanhf(((const float*)&zc)[e] + ((const float*)&vbc)[e]);
        float c = f * ((const float*)&cp)[e] + u * cn;
        ct[e] = c;
        ht[e] = o * tanhf(c);
    }
    *(float4*)(c_out + (size_t)b * 256 + j) = make_float4(ct[0], ct[1], ct[2], ct[3]);
    *(float4*)(h_out + (size_t)b * 256 + j) = make_float4(ht[0], ht[1], ht[2], ht[3]);

    __half2 p0 = __halves2half2(__float2half_rn(ht[0]), __float2half_rn(ht[1]));
    __half2 p1 = __halves2half2(__float2half_rn(ht[2]), __float2half_rn(ht[3]));
    __half2* d = (__half2*)(Alog + (size_t)b * KLOG + j);
    d[0] = p0; d[1] = p1;
}

// ============================================================================
// Launch
// ============================================================================
extern "C" void kernel_launch(void* const* d_in, const int* in_sizes, int n_in,
                              void* d_out, int out_size)
{
    const float* x      = (const float*)d_in[0];
    const float* c_prev = (const float*)d_in[1];
    const float* h_prev = (const float*)d_in[2];
    const float* Wf     = (const float*)d_in[3];
    const float* bf     = (const float*)d_in[4];
    const float* Wu     = (const float*)d_in[5];
    const float* bu     = (const float*)d_in[6];
    const float* Wo     = (const float*)d_in[7];
    const float* bo     = (const float*)d_in[8];
    const float* Wc     = (const float*)d_in[9];
    const float* bc     = (const float*)d_in[10];
    const float* Wl     = (const float*)d_in[11];
    const float* bl     = (const float*)d_in[12];

    float* out   = (float*)d_out;
    float* c_out = out;
    float* h_out = out + (size_t)BATCH * HID;
    float* y_out = out + (size_t)2 * BATCH * HID;

    __half *blog, *alog, *bgate, *agate; float* zbuf;
    cudaGetSymbolAddress((void**)&blog,  g_Blog);
    cudaGetSymbolAddress((void**)&alog,  g_Alog);
    cudaGetSymbolAddress((void**)&bgate, g_Bgate);
    cudaGetSymbolAddress((void**)&agate, g_Agate);
    cudaGetSymbolAddress((void**)&zbuf,  g_z);

    cudaFuncSetAttribute(gemm_f16<KGATE, false>,
                         cudaFuncAttributeMaxDynamicSharedMemorySize, T_SMEM);
    cudaFuncSetAttribute(gemm_f16<KLOG, true>,
                         cudaFuncAttributeMaxDynamicSharedMemorySize, T_SMEM);

    // 1) packs
    pack_B_gates<<<(1024 * 192 + 255) / 256, 256>>>(Wf, Wu, Wo, Wc, bgate);
    pack_A_gates<<<(BATCH * 192 + 255) / 256, 256>>>(x, c_prev, h_prev, agate);
    pack_B_logits<<<(VOCAB * 64 + 255) / 256, 256>>>(Wl, blog);

    // 2) gates GEMM: z = Agate . Bgate^T   [8192, 1024]
    {
        dim3 g(1024 / T_BN, BATCH / T_BM);   // (4, 64)
        gemm_f16<KGATE, false><<<g, T_THREADS, T_SMEM>>>(agate, bgate, nullptr, zbuf, 1024);
    }
    // 3) combine -> c_t, h_t, Alog
    gate_combine<<<(BATCH * 64 + 255) / 256, 256>>>(zbuf, c_prev, bf, bu, bo, bc,
                                                    c_out, h_out, alog);
    // 4) logits GEMM: y = Alog . Blog^T + bl   [8192, 32000]
    {
        dim3 g(VOCAB / T_BN, BATCH / T_BM);  // (125, 64)
        gemm_f16<KLOG, true><<<g, T_THREADS, T_SMEM>>>(alog, blog, bl, y_out, VOCAB);
    }
}